// round 1
// baseline (speedup 1.0000x reference)
#include <cuda_runtime.h>

#define N_IN   256
#define N_H    128
#define MAX_NODES 100000

// ---------------- scratch (allocation-free: __device__ globals) ----------------
__device__ float g_H  [2u * MAX_NODES * N_H];   // pre-aggregation features [2N, 128]
__device__ float g_AGG[2u * MAX_NODES * N_H];   // aggregated features      [2N, 128]
__device__ float g_wsum[N_H];                   // rowsum of lin_W
__device__ float g_bsum;                        // sum of lin_b

// ---------------- f32x2 packed-FMA helpers (Blackwell) ----------------
typedef unsigned long long u64;

__device__ __forceinline__ u64 pack2(float a, float b) {
    u64 r; asm("mov.b64 %0, {%1, %2};" : "=l"(r) : "f"(a), "f"(b)); return r;
}
__device__ __forceinline__ void fma2(u64 &d, u64 a, u64 b) {
    asm("fma.rn.f32x2 %0, %1, %2, %3;" : "=l"(d) : "l"(a), "l"(b), "l"(d));
}
__device__ __forceinline__ float2 unpack2(u64 v) {
    float2 r; asm("mov.b64 {%0, %1}, %2;" : "=f"(r.x), "=f"(r.y) : "l"(v)); return r;
}

// ---------------- prep: wsum[k] = sum_j lin_W[k][j]; bsum = sum lin_b ----------------
__global__ void prep_kernel(const float* __restrict__ linW, const float* __restrict__ linb)
{
    int tid  = threadIdx.x;          // 256 threads
    int warp = tid >> 5, lane = tid & 31;
    for (int k = warp; k < N_H; k += 8) {
        float s = 0.f;
        #pragma unroll
        for (int j = lane; j < N_H; j += 32) s += linW[k * N_H + j];
        #pragma unroll
        for (int o = 16; o > 0; o >>= 1) s += __shfl_down_sync(0xffffffffu, s, o);
        if (lane == 0) g_wsum[k] = s;
    }
    __shared__ float sb[256];
    sb[tid] = (tid < N_H) ? linb[tid] : 0.f;
    __syncthreads();
    for (int o = 128; o > 0; o >>= 1) { if (tid < o) sb[tid] += sb[tid + o]; __syncthreads(); }
    if (tid == 0) g_bsum = sb[0];
}

// ---------------- zero AGG ----------------
__global__ void zero_kernel(int n_f4)
{
    int i = blockIdx.x * blockDim.x + threadIdx.x;
    if (i < n_f4) reinterpret_cast<float4*>(g_AGG)[i] = make_float4(0.f, 0.f, 0.f, 0.f);
}

// ---------------- GEMM: g_H = [x1;x2] @ W  (M x 256 @ 256 x 128) ----------------
// BM=128, BN=128 (full N), BK=16, 256 threads, 8x8 per-thread tile via f32x2 packed FMA.
__global__ __launch_bounds__(256) void gemm_kernel(
    const float* __restrict__ x1, const float* __restrict__ x2,
    const float* __restrict__ W, int n_nodes)
{
    __shared__ float As[16][128];
    __shared__ float Bs[16][128];
    const int m_tot = 2 * n_nodes;
    const int tid = threadIdx.x;
    const int tx = tid & 15, ty = tid >> 4;
    const int blockRow = blockIdx.x * 128;

    u64 acc[8][4];
    #pragma unroll
    for (int i = 0; i < 8; i++)
        #pragma unroll
        for (int j = 0; j < 4; j++) acc[i][j] = 0ull;  // (0.0f, 0.0f)

    for (int kc = 0; kc < 16; kc++) {
        const int k0 = kc * 16;
        // load A tile (transpose into As[k][m])
        #pragma unroll
        for (int t = 0; t < 2; t++) {
            int idx = tid + t * 256;           // 0..511
            int m   = idx >> 2;                // 0..127
            int kk4 = (idx & 3) * 4;
            int mg  = blockRow + m;
            float4 v = make_float4(0.f, 0.f, 0.f, 0.f);
            if (mg < m_tot) {
                const float* src = (mg < n_nodes)
                    ? (x1 + (size_t)mg * N_IN)
                    : (x2 + (size_t)(mg - n_nodes) * N_IN);
                v = *reinterpret_cast<const float4*>(src + k0 + kk4);
            }
            As[kk4 + 0][m] = v.x; As[kk4 + 1][m] = v.y;
            As[kk4 + 2][m] = v.z; As[kk4 + 3][m] = v.w;
        }
        // load B tile (direct copy)
        #pragma unroll
        for (int t = 0; t < 2; t++) {
            int idx = tid + t * 256;
            int kk  = idx >> 5;                // 0..15
            int n4  = (idx & 31) * 4;
            *reinterpret_cast<float4*>(&Bs[kk][n4]) =
                *reinterpret_cast<const float4*>(W + (size_t)(k0 + kk) * N_H + n4);
        }
        __syncthreads();
        #pragma unroll
        for (int kk = 0; kk < 16; kk++) {
            float4 a0 = *reinterpret_cast<const float4*>(&As[kk][ty * 8]);
            float4 a1 = *reinterpret_cast<const float4*>(&As[kk][ty * 8 + 4]);
            float4 b0 = *reinterpret_cast<const float4*>(&Bs[kk][tx * 8]);
            float4 b1 = *reinterpret_cast<const float4*>(&Bs[kk][tx * 8 + 4]);
            u64 bp[4] = { pack2(b0.x, b0.y), pack2(b0.z, b0.w),
                          pack2(b1.x, b1.y), pack2(b1.z, b1.w) };
            float av[8] = { a0.x, a0.y, a0.z, a0.w, a1.x, a1.y, a1.z, a1.w };
            #pragma unroll
            for (int i = 0; i < 8; i++) {
                u64 ap = pack2(av[i], av[i]);
                #pragma unroll
                for (int j = 0; j < 4; j++) fma2(acc[i][j], ap, bp[j]);
            }
        }
        __syncthreads();
    }
    // epilogue
    #pragma unroll
    for (int i = 0; i < 8; i++) {
        int mg = blockRow + ty * 8 + i;
        if (mg >= m_tot) continue;
        float* dst = g_H + (size_t)mg * N_H + tx * 8;
        float2 p0 = unpack2(acc[i][0]), p1 = unpack2(acc[i][1]);
        float2 p2 = unpack2(acc[i][2]), p3 = unpack2(acc[i][3]);
        *reinterpret_cast<float4*>(dst)     = make_float4(p0.x, p0.y, p1.x, p1.y);
        *reinterpret_cast<float4*>(dst + 4) = make_float4(p2.x, p2.y, p3.x, p3.y);
    }
}

// ---------------- SpMM: agg[r] += w * H[c] (both passes), warp per edge ----------------
__global__ __launch_bounds__(256) void spmm_kernel(
    const int* __restrict__ ei, const float* __restrict__ ew,
    int n_edges, int n_nodes)
{
    int warp = (blockIdx.x * blockDim.x + threadIdx.x) >> 5;
    int lane = threadIdx.x & 31;
    if (warp >= n_edges) return;
    int   r  = __ldg(ei + warp);
    int   c  = __ldg(ei + n_edges + warp);
    float we = __ldg(ew + warp);

    float4 v1 = reinterpret_cast<const float4*>(g_H + (size_t)c * N_H)[lane];
    float4 v2 = reinterpret_cast<const float4*>(g_H + (size_t)(c + n_nodes) * N_H)[lane];

    float* d1 = g_AGG + (size_t)r * N_H + lane * 4;
    float* d2 = g_AGG + (size_t)(r + n_nodes) * N_H + lane * 4;

    asm volatile("red.global.add.v4.f32 [%0], {%1, %2, %3, %4};"
                 :: "l"(d1), "f"(we * v1.x), "f"(we * v1.y), "f"(we * v1.z), "f"(we * v1.w)
                 : "memory");
    asm volatile("red.global.add.v4.f32 [%0], {%1, %2, %3, %4};"
                 :: "l"(d2), "f"(we * v2.x), "f"(we * v2.y), "f"(we * v2.z), "f"(we * v2.w)
                 : "memory");
}

// ---------------- finalize: z[i] = dot(prelu(agg[i]+bias), wsum) + bsum ----------------
__global__ __launch_bounds__(256) void final_kernel(
    const float* __restrict__ bias, const float* __restrict__ pa,
    float* __restrict__ out, int m_tot)
{
    int warp = (blockIdx.x * blockDim.x + threadIdx.x) >> 5;
    int lane = threadIdx.x & 31;
    if (warp >= m_tot) return;
    float a  = __ldg(pa);
    float4 v = *reinterpret_cast<const float4*>(g_AGG + (size_t)warp * N_H + lane * 4);
    float4 b = __ldg(reinterpret_cast<const float4*>(bias) + lane);
    float4 w = *reinterpret_cast<const float4*>(g_wsum + lane * 4);
    float s = 0.f, t;
    t = v.x + b.x; t = (t >= 0.f) ? t : a * t; s += t * w.x;
    t = v.y + b.y; t = (t >= 0.f) ? t : a * t; s += t * w.y;
    t = v.z + b.z; t = (t >= 0.f) ? t : a * t; s += t * w.z;
    t = v.w + b.w; t = (t >= 0.f) ? t : a * t; s += t * w.w;
    #pragma unroll
    for (int o = 16; o > 0; o >>= 1) s += __shfl_down_sync(0xffffffffu, s, o);
    if (lane == 0) out[warp] = s + g_bsum;
}

// ---------------- launcher ----------------
extern "C" void kernel_launch(void* const* d_in, const int* in_sizes, int n_in,
                              void* d_out, int out_size)
{
    const float* x1 = (const float*)d_in[0];
    const float* x2 = (const float*)d_in[1];
    const int*   ei = (const int*)  d_in[2];
    const float* ew = (const float*)d_in[3];
    const float* Wg = (const float*)d_in[4];
    const float* gb = (const float*)d_in[5];
    const float* pa = (const float*)d_in[6];
    const float* lW = (const float*)d_in[7];
    const float* lb = (const float*)d_in[8];
    float* out = (float*)d_out;

    const int n_nodes = in_sizes[0] / N_IN;        // 100000
    const int n_edges = in_sizes[3];               // 800000
    const int m_tot   = 2 * n_nodes;

    // zero agg scratch
    int n_f4 = m_tot * N_H / 4;
    zero_kernel<<<(n_f4 + 255) / 256, 256>>>(n_f4);

    // lin_W rowsum / lin_b sum
    prep_kernel<<<1, 256>>>(lW, lb);

    // H = [x1;x2] @ W
    gemm_kernel<<<(m_tot + 127) / 128, 256>>>(x1, x2, Wg, n_nodes);

    // scatter-add aggregation
    {
        long long threads = (long long)n_edges * 32;
        int blocks = (int)((threads + 255) / 256);
        spmm_kernel<<<blocks, 256>>>(ei, ew, n_edges, n_nodes);
    }

    // epilogue
    {
        long long threads = (long long)m_tot * 32;
        int blocks = (int)((threads + 255) / 256);
        final_kernel<<<blocks, 256>>>(gb, pa, out, m_tot);
    }
}

// round 3
// speedup vs baseline: 1.6671x; 1.6671x over previous
#include <cuda_runtime.h>
#include <cuda_bf16.h>
#include <mma.h>
#include <cstdint>

using namespace nvcuda;

#define N_IN   256
#define N_H    128
#define MAX_NODES 100000
#define MAX_EDGES 800000

// ---------------- scratch (allocation-free: __device__ globals) ----------------
// g_H has 128 pad rows so the last (partial) GEMM tile can store unguarded.
__device__ float g_H[(2u * MAX_NODES + 128) * N_H];     // features [2N, 128] (+pad)
__device__ __nv_bfloat16 g_Wh[N_IN * N_H];              // W split hi (bf16)
__device__ __nv_bfloat16 g_Wl[N_IN * N_H];              // W split lo (bf16)
__device__ float g_wsum[N_H];                           // rowsum of lin_W
__device__ float g_bsum;                                // sum of lin_b
// CSR scratch
__device__ int   g_deg[MAX_NODES + 1];
__device__ int   g_rowptr[MAX_NODES + 1];
__device__ int   g_fill[MAX_NODES];
__device__ int   g_blk[256];
__device__ int   g_ecol[MAX_EDGES];
__device__ float g_ewt[MAX_EDGES];

// =======================================================================
//  CSR construction
// =======================================================================
__global__ void zero_deg_kernel(int n1)
{
    int i = blockIdx.x * blockDim.x + threadIdx.x;
    if (i < n1) g_deg[i] = 0;
}

__global__ void hist_kernel(const int* __restrict__ ei, int n_edges)
{
    int i = blockIdx.x * blockDim.x + threadIdx.x;
    if (i < n_edges) atomicAdd(&g_deg[__ldg(ei + i)], 1);
}

// block-wise exclusive scan (1024 threads/block)
__global__ __launch_bounds__(1024) void scan_partial_kernel(int n, int n1)
{
    int tid  = threadIdx.x;
    int gid  = blockIdx.x * 1024 + tid;
    int lane = tid & 31, wid = tid >> 5;
    int v = (gid < n) ? g_deg[gid] : 0;
    int inc = v;
    #pragma unroll
    for (int o = 1; o < 32; o <<= 1) {
        int t = __shfl_up_sync(0xffffffffu, inc, o);
        if (lane >= o) inc += t;
    }
    __shared__ int ws[32];
    if (lane == 31) ws[wid] = inc;
    __syncthreads();
    if (wid == 0) {
        int s = ws[lane];
        #pragma unroll
        for (int o = 1; o < 32; o <<= 1) {
            int t = __shfl_up_sync(0xffffffffu, s, o);
            if (lane >= o) s += t;
        }
        ws[lane] = s;
    }
    __syncthreads();
    int woff = wid ? ws[wid - 1] : 0;
    int excl = woff + inc - v;
    if (gid < n1) g_rowptr[gid] = excl;
    if (tid == 1023) g_blk[blockIdx.x] = woff + inc;
}

__global__ void scan_blk_kernel(int nb)
{
    if (threadIdx.x == 0 && blockIdx.x == 0) {
        int run = 0;
        for (int b = 0; b < nb; b++) { int t = g_blk[b]; g_blk[b] = run; run += t; }
    }
}

__global__ __launch_bounds__(1024) void scan_add_kernel(int n, int n1)
{
    int gid = blockIdx.x * 1024 + threadIdx.x;
    if (gid < n1) {
        int r = g_rowptr[gid] + g_blk[blockIdx.x];
        g_rowptr[gid] = r;
        if (gid < n) g_fill[gid] = r;
    }
}

__global__ void scatter_kernel(const int* __restrict__ ei, const float* __restrict__ ew,
                               int n_edges)
{
    int i = blockIdx.x * blockDim.x + threadIdx.x;
    if (i >= n_edges) return;
    int   r = __ldg(ei + i);
    int   c = __ldg(ei + n_edges + i);
    float w = __ldg(ew + i);
    int p = atomicAdd(&g_fill[r], 1);
    g_ecol[p] = c;
    g_ewt[p]  = w;
}

// =======================================================================
//  prep: wsum / bsum + W bf16 split
// =======================================================================
__global__ void prep_kernel(const float* __restrict__ linW, const float* __restrict__ linb)
{
    int tid  = threadIdx.x;          // 256 threads
    int warp = tid >> 5, lane = tid & 31;
    for (int k = warp; k < N_H; k += 8) {
        float s = 0.f;
        #pragma unroll
        for (int j = lane; j < N_H; j += 32) s += linW[k * N_H + j];
        #pragma unroll
        for (int o = 16; o > 0; o >>= 1) s += __shfl_down_sync(0xffffffffu, s, o);
        if (lane == 0) g_wsum[k] = s;
    }
    __shared__ float sb[256];
    sb[tid] = (tid < N_H) ? linb[tid] : 0.f;
    __syncthreads();
    for (int o = 128; o > 0; o >>= 1) { if (tid < o) sb[tid] += sb[tid + o]; __syncthreads(); }
    if (tid == 0) g_bsum = sb[0];
}

__global__ void wsplit_kernel(const float* __restrict__ W)
{
    int i = blockIdx.x * blockDim.x + threadIdx.x;   // 32768 elements
    if (i < N_IN * N_H) {
        float v = __ldg(W + i);
        __nv_bfloat16 h = __float2bfloat16(v);
        __nv_bfloat16 l = __float2bfloat16(v - __bfloat162float(h));
        g_Wh[i] = h;
        g_Wl[i] = l;
    }
}

// =======================================================================
//  GEMM: g_H = [x1;x2] @ W   via wmma bf16 (3-term split)
//  Tile 128x128, K=256 in 4 chunks of 64. 256 threads = 8 warps (2x4).
// =======================================================================
#define A_LD 72   // padded leading dim for smem A (bf16 elements)

__global__ __launch_bounds__(256) void gemm_wmma_kernel(
    const float* __restrict__ x1, const float* __restrict__ x2, int n_nodes)
{
    __shared__ __nv_bfloat16 Ah[128][A_LD];
    __shared__ __nv_bfloat16 Al[128][A_LD];

    const int m_tot = 2 * n_nodes;
    const int tid = threadIdx.x;
    const int wid = tid >> 5;
    const int warp_m = wid & 1;       // 0..1 -> 64 rows each
    const int warp_n = wid >> 1;      // 0..3 -> 32 cols each
    const int blockRow = blockIdx.x * 128;

    wmma::fragment<wmma::accumulator, 16, 16, 16, float> acc[4][2];
    #pragma unroll
    for (int mi = 0; mi < 4; mi++)
        #pragma unroll
        for (int ni = 0; ni < 2; ni++)
            wmma::fill_fragment(acc[mi][ni], 0.f);

    for (int ch = 0; ch < 4; ch++) {
        const int k0 = ch * 64;
        // ---- stage A chunk [128 x 64], split into bf16 hi/lo ----
        #pragma unroll
        for (int t = 0; t < 8; t++) {
            int e   = t * 256 + tid;           // 0..2047 float4 slots
            int row = e >> 4;                  // 0..127
            int c4  = e & 15;                  // 0..15
            int mg  = blockRow + row;
            float4 v = make_float4(0.f, 0.f, 0.f, 0.f);
            if (mg < m_tot) {
                const float* src = (mg < n_nodes)
                    ? (x1 + (size_t)mg * N_IN)
                    : (x2 + (size_t)(mg - n_nodes) * N_IN);
                v = *reinterpret_cast<const float4*>(src + k0 + c4 * 4);
            }
            __nv_bfloat16 h0 = __float2bfloat16(v.x), l0 = __float2bfloat16(v.x - __bfloat162float(h0));
            __nv_bfloat16 h1 = __float2bfloat16(v.y), l1 = __float2bfloat16(v.y - __bfloat162float(h1));
            __nv_bfloat16 h2 = __float2bfloat16(v.z), l2 = __float2bfloat16(v.z - __bfloat162float(h2));
            __nv_bfloat16 h3 = __float2bfloat16(v.w), l3 = __float2bfloat16(v.w - __bfloat162float(h3));
            __nv_bfloat16* ph = &Ah[row][c4 * 4];
            __nv_bfloat16* pl = &Al[row][c4 * 4];
            ph[0] = h0; ph[1] = h1; ph[2] = h2; ph[3] = h3;
            pl[0] = l0; pl[1] = l1; pl[2] = l2; pl[3] = l3;
        }
        __syncthreads();

        // ---- MMA over 4 k-steps of 16 ----
        #pragma unroll
        for (int ks = 0; ks < 4; ks++) {
            const int kk = ks * 16;
            wmma::fragment<wmma::matrix_a, 16, 16, 16, __nv_bfloat16, wmma::row_major> ah[4], al[4];
            #pragma unroll
            for (int mi = 0; mi < 4; mi++) {
                int r0 = warp_m * 64 + mi * 16;
                wmma::load_matrix_sync(ah[mi], &Ah[r0][kk], A_LD);
                wmma::load_matrix_sync(al[mi], &Al[r0][kk], A_LD);
            }
            #pragma unroll
            for (int ni = 0; ni < 2; ni++) {
                int c0 = warp_n * 32 + ni * 16;
                wmma::fragment<wmma::matrix_b, 16, 16, 16, __nv_bfloat16, wmma::row_major> bh, bl;
                wmma::load_matrix_sync(bh, g_Wh + (size_t)(k0 + kk) * N_H + c0, N_H);
                wmma::load_matrix_sync(bl, g_Wl + (size_t)(k0 + kk) * N_H + c0, N_H);
                #pragma unroll
                for (int mi = 0; mi < 4; mi++) {
                    wmma::mma_sync(acc[mi][ni], ah[mi], bh, acc[mi][ni]);
                    wmma::mma_sync(acc[mi][ni], ah[mi], bl, acc[mi][ni]);
                    wmma::mma_sync(acc[mi][ni], al[mi], bh, acc[mi][ni]);
                }
            }
        }
        __syncthreads();
    }

    // ---- epilogue: store straight to g_H (pad rows absorb the partial tile) ----
    #pragma unroll
    for (int mi = 0; mi < 4; mi++) {
        int r0 = blockRow + warp_m * 64 + mi * 16;
        #pragma unroll
        for (int ni = 0; ni < 2; ni++) {
            int c0 = warp_n * 32 + ni * 16;
            wmma::store_matrix_sync(g_H + (size_t)r0 * N_H + c0, acc[mi][ni],
                                    N_H, wmma::mem_row_major);
        }
    }
}

// =======================================================================
//  Fused gather-SpMM + epilogue: warp per row
//  z[i] = dot(prelu(sum_e w_e H[c_e] + bias), wsum) + bsum   (both passes)
// =======================================================================
__global__ __launch_bounds__(256) void gather_final_kernel(
    const float* __restrict__ bias, const float* __restrict__ pa,
    float* __restrict__ out, int n_nodes)
{
    int row  = (blockIdx.x * blockDim.x + threadIdx.x) >> 5;
    int lane = threadIdx.x & 31;
    if (row >= n_nodes) return;

    int s = __ldg(&g_rowptr[row]);
    int e = __ldg(&g_rowptr[row + 1]);

    float4 a1 = make_float4(0.f, 0.f, 0.f, 0.f);
    float4 a2 = make_float4(0.f, 0.f, 0.f, 0.f);

    int j = s;
    for (; j + 1 < e; j += 2) {
        int   c0 = __ldg(&g_ecol[j]),     c1 = __ldg(&g_ecol[j + 1]);
        float w0 = __ldg(&g_ewt[j]),      w1 = __ldg(&g_ewt[j + 1]);
        float4 u1 = reinterpret_cast<const float4*>(g_H + (size_t)c0 * N_H)[lane];
        float4 u2 = reinterpret_cast<const float4*>(g_H + (size_t)(c0 + n_nodes) * N_H)[lane];
        float4 v1 = reinterpret_cast<const float4*>(g_H + (size_t)c1 * N_H)[lane];
        float4 v2 = reinterpret_cast<const float4*>(g_H + (size_t)(c1 + n_nodes) * N_H)[lane];
        a1.x += w0 * u1.x + w1 * v1.x;  a1.y += w0 * u1.y + w1 * v1.y;
        a1.z += w0 * u1.z + w1 * v1.z;  a1.w += w0 * u1.w + w1 * v1.w;
        a2.x += w0 * u2.x + w1 * v2.x;  a2.y += w0 * u2.y + w1 * v2.y;
        a2.z += w0 * u2.z + w1 * v2.z;  a2.w += w0 * u2.w + w1 * v2.w;
    }
    if (j < e) {
        int   c0 = __ldg(&g_ecol[j]);
        float w0 = __ldg(&g_ewt[j]);
        float4 u1 = reinterpret_cast<const float4*>(g_H + (size_t)c0 * N_H)[lane];
        float4 u2 = reinterpret_cast<const float4*>(g_H + (size_t)(c0 + n_nodes) * N_H)[lane];
        a1.x += w0 * u1.x;  a1.y += w0 * u1.y;  a1.z += w0 * u1.z;  a1.w += w0 * u1.w;
        a2.x += w0 * u2.x;  a2.y += w0 * u2.y;  a2.z += w0 * u2.z;  a2.w += w0 * u2.w;
    }

    float  a = __ldg(pa);
    float4 b = __ldg(reinterpret_cast<const float4*>(bias) + lane);
    float4 w = *reinterpret_cast<const float4*>(g_wsum + lane * 4);

    float s1 = 0.f, s2 = 0.f, t;
    t = a1.x + b.x; t = (t >= 0.f) ? t : a * t; s1 += t * w.x;
    t = a1.y + b.y; t = (t >= 0.f) ? t : a * t; s1 += t * w.y;
    t = a1.z + b.z; t = (t >= 0.f) ? t : a * t; s1 += t * w.z;
    t = a1.w + b.w; t = (t >= 0.f) ? t : a * t; s1 += t * w.w;
    t = a2.x + b.x; t = (t >= 0.f) ? t : a * t; s2 += t * w.x;
    t = a2.y + b.y; t = (t >= 0.f) ? t : a * t; s2 += t * w.y;
    t = a2.z + b.z; t = (t >= 0.f) ? t : a * t; s2 += t * w.z;
    t = a2.w + b.w; t = (t >= 0.f) ? t : a * t; s2 += t * w.w;

    #pragma unroll
    for (int o = 16; o > 0; o >>= 1) {
        s1 += __shfl_down_sync(0xffffffffu, s1, o);
        s2 += __shfl_down_sync(0xffffffffu, s2, o);
    }
    if (lane == 0) {
        out[row]           = s1 + g_bsum;
        out[row + n_nodes] = s2 + g_bsum;
    }
}

// =======================================================================
//  launcher
// =======================================================================
extern "C" void kernel_launch(void* const* d_in, const int* in_sizes, int n_in,
                              void* d_out, int out_size)
{
    const float* x1 = (const float*)d_in[0];
    const float* x2 = (const float*)d_in[1];
    const int*   ei = (const int*)  d_in[2];
    const float* ew = (const float*)d_in[3];
    const float* Wg = (const float*)d_in[4];
    const float* gb = (const float*)d_in[5];
    const float* pa = (const float*)d_in[6];
    const float* lW = (const float*)d_in[7];
    const float* lb = (const float*)d_in[8];
    float* out = (float*)d_out;

    const int n_nodes = in_sizes[0] / N_IN;        // 100000
    const int n_edges = in_sizes[3];               // 800000
    const int m_tot   = 2 * n_nodes;
    const int n1      = n_nodes + 1;
    const int nb      = (n1 + 1023) / 1024;        // scan blocks

    // ---- CSR build ----
    zero_deg_kernel<<<(n1 + 255) / 256, 256>>>(n1);
    hist_kernel<<<(n_edges + 255) / 256, 256>>>(ei, n_edges);
    scan_partial_kernel<<<nb, 1024>>>(n_nodes, n1);
    scan_blk_kernel<<<1, 32>>>(nb);
    scan_add_kernel<<<nb, 1024>>>(n_nodes, n1);
    scatter_kernel<<<(n_edges + 255) / 256, 256>>>(ei, ew, n_edges);

    // ---- prep: wsum/bsum + W split ----
    prep_kernel<<<1, 256>>>(lW, lb);
    wsplit_kernel<<<(N_IN * N_H + 255) / 256, 256>>>(Wg);

    // ---- GEMM (wmma bf16, 3-term split) ----
    gemm_wmma_kernel<<<(m_tot + 127) / 128, 256>>>(x1, x2, n_nodes);

    // ---- fused gather + epilogue ----
    {
        long long threads = (long long)n_nodes * 32;
        int blocks = (int)((threads + 255) / 256);
        gather_final_kernel<<<blocks, 256>>>(gb, pa, out, n_nodes);
    }
}